// round 2
// baseline (speedup 1.0000x reference)
#include <cuda_runtime.h>
#include <cstdint>

// Problem constants
#define BATCH 64
#define HDIM 56
#define WDIM 56
#define CDIM 256
#define ROUTES 4
#define CONV_OUT 64
#define ROUTE_W 64            // C / ROUTES
#define ROWG 14               // row groups per image (4 rows each)
#define ROWS_PER_G 4
#define NSTAT 9
#define BN_EPS 1e-3f

// Scratch (device globals — no allocation allowed)
__device__ float g_part[BATCH * ROWG * NSTAT * CDIM];   // partial stats, fully overwritten each call
__device__ float g_W[9 * CDIM * ROUTES];                // folded conv@fc weights / 784
__device__ int   g_route[BATCH];

// ---------------------------------------------------------------------------
// Kernel 1: per-(batch, rowgroup, channel) sufficient statistics.
// stats j: 0=EE 1=EO 2=OE 3=OO 4=R0E 5=R0O 6=C0E 7=C0O 8=P00
// ---------------------------------------------------------------------------
__global__ __launch_bounds__(CDIM) void k_stats(const float* __restrict__ in)
{
    const int b  = blockIdx.y;
    const int g  = blockIdx.x;
    const int ci = threadIdx.x;

    const float* base = in + ((size_t)b * HDIM * WDIM) * CDIM + ci;

    float EE = 0.f, EO = 0.f, OE = 0.f, OO = 0.f;
    float R0E = 0.f, R0O = 0.f, C0E = 0.f, C0O = 0.f, P00 = 0.f;

    #pragma unroll
    for (int hh = 0; hh < ROWS_PER_G; ++hh) {
        const int h = g * ROWS_PER_G + hh;
        const float* row = base + (size_t)h * WDIM * CDIM;
        float sE = 0.f, sO = 0.f;
        float v0 = row[0];
        #pragma unroll 7
        for (int w = 0; w < WDIM; w += 2) {
            float a  = row[(size_t)w * CDIM];
            float bb = row[(size_t)(w + 1) * CDIM];
            sE += a;
            sO += bb;
        }
        if (h & 1) { OE += sE; OO += sO; C0O += v0; }
        else       { EE += sE; EO += sO; C0E += v0; }
        if (h == 0) { R0E = sE; R0O = sO; P00 = v0; }
    }

    float* p = g_part + (((size_t)b * ROWG + g) * NSTAT) * CDIM + ci;
    p[0 * CDIM] = EE;  p[1 * CDIM] = EO;  p[2 * CDIM] = OE;
    p[3 * CDIM] = OO;  p[4 * CDIM] = R0E; p[5 * CDIM] = R0O;
    p[6 * CDIM] = C0E; p[7 * CDIM] = C0O; p[8 * CDIM] = P00;
}

// ---------------------------------------------------------------------------
// Kernel 2: fold conv_w [3,3,256,64] with fc_w [64,4]:
//   g_W[k][ci][r] = (1/784) * sum_co conv_w[k][ci][co] * fc_w[co][r]
// ---------------------------------------------------------------------------
__global__ __launch_bounds__(CDIM) void k_weff(const float* __restrict__ conv_w,
                                               const float* __restrict__ fc_w)
{
    __shared__ float sf[CONV_OUT * ROUTES];   // 256 floats
    const int k  = blockIdx.x;
    const int ci = threadIdx.x;
    sf[ci] = fc_w[ci];
    __syncthreads();

    const float* cw = conv_w + ((size_t)k * CDIM + ci) * CONV_OUT;
    float acc0 = 0.f, acc1 = 0.f, acc2 = 0.f, acc3 = 0.f;
    #pragma unroll 16
    for (int co = 0; co < CONV_OUT; ++co) {
        float wv = cw[co];
        acc0 += wv * sf[co * 4 + 0];
        acc1 += wv * sf[co * 4 + 1];
        acc2 += wv * sf[co * 4 + 2];
        acc3 += wv * sf[co * 4 + 3];
    }
    const float inv = 1.0f / 784.0f;
    float* o = g_W + ((size_t)k * CDIM + ci) * ROUTES;
    o[0] = acc0 * inv; o[1] = acc1 * inv; o[2] = acc2 * inv; o[3] = acc3 * inv;
}

// ---------------------------------------------------------------------------
// Kernel 3: per-batch routing logits + argmax.
// One block per batch, thread = channel.
// ---------------------------------------------------------------------------
__global__ __launch_bounds__(CDIM) void k_route(const float* __restrict__ gamma,
                                                const float* __restrict__ beta,
                                                const float* __restrict__ mmean,
                                                const float* __restrict__ mvar,
                                                const float* __restrict__ conv_b,
                                                const float* __restrict__ fc_w,
                                                const float* __restrict__ fc_b,
                                                float* __restrict__ out_routing)
{
    const int b  = blockIdx.x;
    const int ci = threadIdx.x;

    // Folded weights for this channel: W[k][r], k = kh*3+kw
    float W[9][ROUTES];
    #pragma unroll
    for (int k = 0; k < 9; ++k) {
        const float* w = g_W + ((size_t)k * CDIM + ci) * ROUTES;
        #pragma unroll
        for (int r = 0; r < ROUTES; ++r) W[k][r] = w[r];
    }

    const float scale = rsqrtf(mvar[ci] + BN_EPS) * gamma[ci];
    const float offs  = beta[ci] - mmean[ci] * scale;

    // Sum partial stats over the 14 row-groups
    float st[NSTAT];
    #pragma unroll
    for (int j = 0; j < NSTAT; ++j) st[j] = 0.f;
    const float* p = g_part + ((size_t)b * ROWG) * NSTAT * CDIM + ci;
    #pragma unroll
    for (int g = 0; g < ROWG; ++g) {
        #pragma unroll
        for (int j = 0; j < NSTAT; ++j)
            st[j] += p[((size_t)g * NSTAT + j) * CDIM];
    }

    float acc[ROUTES];
    #pragma unroll
    for (int r = 0; r < ROUTES; ++r) {
        // Inclusion-exclusion coefficients (k = kh*3 + kw)
        float tEE  = W[0][r] + W[2][r] + W[6][r] + W[8][r];
        float tEO  = W[1][r] + W[7][r];
        float tOE  = W[3][r] + W[5][r];
        float tOO  = W[4][r];
        float tR0E = -(W[6][r] + W[8][r]);
        float tR0O = -W[7][r];
        float tC0E = -(W[2][r] + W[8][r]);
        float tC0O = -W[5][r];
        float tP   = W[8][r];

        float dotv = st[0]*tEE + st[1]*tEO + st[2]*tOE + st[3]*tOO
                   + st[4]*tR0E + st[5]*tR0O + st[6]*tC0E + st[7]*tC0O
                   + st[8]*tP;

        // valid-count-weighted sum for the BN offset term
        // n(kh)*n(kw): k0,k1,k3,k4 -> 784; k2,k5,k6,k7 -> 756; k8 -> 729
        float nsum = 784.f * (W[0][r] + W[1][r] + W[3][r] + W[4][r])
                   + 756.f * (W[2][r] + W[5][r] + W[6][r] + W[7][r])
                   + 729.f *  W[8][r];

        acc[r] = scale * dotv + offs * nsum;
    }

    // Bias terms: conv_b through fc (threads 0..63), and fc_b (thread 0)
    if (ci < CONV_OUT) {
        float cb = conv_b[ci];
        #pragma unroll
        for (int r = 0; r < ROUTES; ++r) acc[r] += cb * fc_w[ci * ROUTES + r];
    }
    if (ci == 0) {
        #pragma unroll
        for (int r = 0; r < ROUTES; ++r) acc[r] += fc_b[r];
    }

    // Block reduction over 256 channels
    #pragma unroll
    for (int r = 0; r < ROUTES; ++r) {
        #pragma unroll
        for (int o = 16; o > 0; o >>= 1)
            acc[r] += __shfl_xor_sync(0xFFFFFFFFu, acc[r], o);
    }
    __shared__ float red[8][ROUTES];
    const int wid = ci >> 5, lane = ci & 31;
    if (lane == 0) {
        #pragma unroll
        for (int r = 0; r < ROUTES; ++r) red[wid][r] = acc[r];
    }
    __syncthreads();
    if (ci == 0) {
        float v[ROUTES];
        #pragma unroll
        for (int r = 0; r < ROUTES; ++r) {
            float s = 0.f;
            #pragma unroll
            for (int w = 0; w < 8; ++w) s += red[w][r];
            v[r] = s;
        }
        int best = 0;
        float bv = v[0];
        #pragma unroll
        for (int r = 1; r < ROUTES; ++r)
            if (v[r] > bv) { bv = v[r]; best = r; }
        g_route[b] = best;
        #pragma unroll
        for (int r = 0; r < ROUTES; ++r) out_routing[b * ROUTES + r] = v[r];
    }
}

// ---------------------------------------------------------------------------
// Kernel 4: gather selected 64-channel slab (float4 copy).
// grid (196, 64), 256 threads; one float4 per thread.
// ---------------------------------------------------------------------------
__global__ __launch_bounds__(256) void k_gather(const float* __restrict__ in,
                                                float* __restrict__ out)
{
    const int b = blockIdx.y;
    const int route = g_route[b];
    const int t = blockIdx.x * 256 + threadIdx.x;   // 0 .. 50175
    const int pixel = t >> 4;
    const int q = t & 15;

    const float4* src = (const float4*)in
        + ((size_t)b * (HDIM * WDIM) + pixel) * (CDIM / 4)
        + route * (ROUTE_W / 4) + q;
    float4* dst = (float4*)out + (size_t)b * (HDIM * WDIM * ROUTE_W / 4) + t;
    *dst = *src;
}

// ---------------------------------------------------------------------------
extern "C" void kernel_launch(void* const* d_in, const int* in_sizes, int n_in,
                              void* d_out, int out_size)
{
    const float* inputs  = (const float*)d_in[0];
    const float* gamma   = (const float*)d_in[1];
    const float* beta    = (const float*)d_in[2];
    const float* mmean   = (const float*)d_in[3];
    const float* mvar    = (const float*)d_in[4];
    const float* conv_w  = (const float*)d_in[5];
    const float* conv_b  = (const float*)d_in[6];
    const float* fc_w    = (const float*)d_in[7];
    const float* fc_b    = (const float*)d_in[8];

    float* out = (float*)d_out;
    // output layout: x [64,56,56,64] then routing_x [64,4]
    float* out_routing = out + ((size_t)out_size - BATCH * ROUTES);

    k_stats<<<dim3(ROWG, BATCH), CDIM>>>(inputs);
    k_weff<<<9, CDIM>>>(conv_w, fc_w);
    k_route<<<BATCH, CDIM>>>(gamma, beta, mmean, mvar, conv_b, fc_w, fc_b, out_routing);
    k_gather<<<dim3((HDIM * WDIM * ROUTE_W / 4) / 256, BATCH), 256>>>(inputs, out);
}

// round 3
// speedup vs baseline: 1.0837x; 1.0837x over previous
#include <cuda_runtime.h>
#include <cstdint>

// Problem constants
#define BATCH 64
#define HDIM 56
#define WDIM 56
#define CDIM 256
#define ROUTES 4
#define CONV_OUT 64
#define ROUTE_W 64            // C / ROUTES
#define ROWG 7                // row groups per image (8 rows each)
#define NSTAT 9
#define BN_EPS 1e-3f

// Scratch (device globals — no allocation allowed)
__device__ float g_part[BATCH * ROWG * NSTAT * CDIM];   // 1.6 MB, fully overwritten each call
__device__ float g_W[9 * CDIM * ROUTES];                // folded conv@fc weights / 784
__device__ int   g_route[BATCH];

// ---------------------------------------------------------------------------
// Kernel 1: per-(batch, rowgroup) sufficient statistics, float4-vectorized.
// Block: 256 threads = 4 row-slices (rr) x 64 channel-quads (c4).
// Each thread: rows h0 = g*8 + rr*2 (even) and h0+1 (odd), channels 4*c4..+3.
// stats j: 0=EE 1=EO 2=OE 3=OO 4=R0E 5=R0O 6=C0E 7=C0O 8=P00
// ---------------------------------------------------------------------------
__global__ __launch_bounds__(256) void k_stats(const float* __restrict__ in)
{
    const int b   = blockIdx.y;
    const int g   = blockIdx.x;          // 0..6
    const int tid = threadIdx.x;
    const int c4  = tid & 63;            // channel quad
    const int rr  = tid >> 6;            // 0..3

    const int h0 = g * 8 + rr * 2;       // always even
    const float4* rowE = (const float4*)(in
        + (((size_t)b * HDIM + h0) * WDIM) * CDIM) + c4;
    const float4* rowO = rowE + (WDIM * CDIM / 4);

    float4 EE = {0,0,0,0}, EO = {0,0,0,0}, OE = {0,0,0,0}, OO = {0,0,0,0};

    #pragma unroll 4
    for (int w = 0; w < WDIM; w += 2) {
        float4 a = rowE[(size_t)w * (CDIM/4)];
        float4 bb = rowE[(size_t)(w + 1) * (CDIM/4)];
        float4 c = rowO[(size_t)w * (CDIM/4)];
        float4 d = rowO[(size_t)(w + 1) * (CDIM/4)];
        EE.x += a.x; EE.y += a.y; EE.z += a.z; EE.w += a.w;
        EO.x += bb.x; EO.y += bb.y; EO.z += bb.z; EO.w += bb.w;
        OE.x += c.x; OE.y += c.y; OE.z += c.z; OE.w += c.w;
        OO.x += d.x; OO.y += d.y; OO.z += d.z; OO.w += d.w;
    }

    float4 C0E = rowE[0];                // col-0 of even row (L1 hit)
    float4 C0O = rowO[0];                // col-0 of odd row
    float4 Z = {0,0,0,0};
    float4 R0E = Z, R0O = Z, P00 = Z;
    if (h0 == 0) { R0E = EE; R0O = EO; P00 = C0E; }

    // In-block reduction over the 4 row-slices via shared memory.
    __shared__ float4 sm[4][NSTAT][64];   // 36 KB
    sm[rr][0][c4] = EE;  sm[rr][1][c4] = EO;  sm[rr][2][c4] = OE;
    sm[rr][3][c4] = OO;  sm[rr][4][c4] = R0E; sm[rr][5][c4] = R0O;
    sm[rr][6][c4] = C0E; sm[rr][7][c4] = C0O; sm[rr][8][c4] = P00;
    __syncthreads();

    if (tid < 64) {
        float4* p = (float4*)(g_part + (((size_t)b * ROWG + g) * NSTAT) * CDIM) + tid;
        #pragma unroll
        for (int j = 0; j < NSTAT; ++j) {
            float4 s0 = sm[0][j][tid];
            float4 s1 = sm[1][j][tid];
            float4 s2 = sm[2][j][tid];
            float4 s3 = sm[3][j][tid];
            float4 s;
            s.x = (s0.x + s1.x) + (s2.x + s3.x);
            s.y = (s0.y + s1.y) + (s2.y + s3.y);
            s.z = (s0.z + s1.z) + (s2.z + s3.z);
            s.w = (s0.w + s1.w) + (s2.w + s3.w);
            p[(size_t)j * (CDIM/4)] = s;
        }
    }
}

// ---------------------------------------------------------------------------
// Kernel 2: fold conv_w [3,3,256,64] with fc_w [64,4]:
//   g_W[k][ci][r] = (1/784) * sum_co conv_w[k][ci][co] * fc_w[co][r]
// ---------------------------------------------------------------------------
__global__ __launch_bounds__(CDIM) void k_weff(const float* __restrict__ conv_w,
                                               const float* __restrict__ fc_w)
{
    __shared__ float sf[CONV_OUT * ROUTES];   // 256 floats
    const int k  = blockIdx.x;
    const int ci = threadIdx.x;
    sf[ci] = fc_w[ci];
    __syncthreads();

    const float* cw = conv_w + ((size_t)k * CDIM + ci) * CONV_OUT;
    float acc0 = 0.f, acc1 = 0.f, acc2 = 0.f, acc3 = 0.f;
    #pragma unroll 16
    for (int co = 0; co < CONV_OUT; ++co) {
        float wv = cw[co];
        acc0 += wv * sf[co * 4 + 0];
        acc1 += wv * sf[co * 4 + 1];
        acc2 += wv * sf[co * 4 + 2];
        acc3 += wv * sf[co * 4 + 3];
    }
    const float inv = 1.0f / 784.0f;
    float* o = g_W + ((size_t)k * CDIM + ci) * ROUTES;
    o[0] = acc0 * inv; o[1] = acc1 * inv; o[2] = acc2 * inv; o[3] = acc3 * inv;
}

// ---------------------------------------------------------------------------
// Kernel 3: per-batch routing logits + argmax.
// One block per batch, thread = channel.
// ---------------------------------------------------------------------------
__global__ __launch_bounds__(CDIM) void k_route(const float* __restrict__ gamma,
                                                const float* __restrict__ beta,
                                                const float* __restrict__ mmean,
                                                const float* __restrict__ mvar,
                                                const float* __restrict__ conv_b,
                                                const float* __restrict__ fc_w,
                                                const float* __restrict__ fc_b,
                                                float* __restrict__ out_routing)
{
    const int b  = blockIdx.x;
    const int ci = threadIdx.x;

    // Folded weights for this channel: W[k][r], k = kh*3+kw
    float W[9][ROUTES];
    #pragma unroll
    for (int k = 0; k < 9; ++k) {
        const float* w = g_W + ((size_t)k * CDIM + ci) * ROUTES;
        #pragma unroll
        for (int r = 0; r < ROUTES; ++r) W[k][r] = w[r];
    }

    const float scale = rsqrtf(mvar[ci] + BN_EPS) * gamma[ci];
    const float offs  = beta[ci] - mmean[ci] * scale;

    // Sum partial stats over the 7 row-groups
    float st[NSTAT];
    #pragma unroll
    for (int j = 0; j < NSTAT; ++j) st[j] = 0.f;
    const float* p = g_part + ((size_t)b * ROWG) * NSTAT * CDIM + ci;
    #pragma unroll
    for (int g = 0; g < ROWG; ++g) {
        #pragma unroll
        for (int j = 0; j < NSTAT; ++j)
            st[j] += p[((size_t)g * NSTAT + j) * CDIM];
    }

    float acc[ROUTES];
    #pragma unroll
    for (int r = 0; r < ROUTES; ++r) {
        // Inclusion-exclusion coefficients (k = kh*3 + kw)
        float tEE  = W[0][r] + W[2][r] + W[6][r] + W[8][r];
        float tEO  = W[1][r] + W[7][r];
        float tOE  = W[3][r] + W[5][r];
        float tOO  = W[4][r];
        float tR0E = -(W[6][r] + W[8][r]);
        float tR0O = -W[7][r];
        float tC0E = -(W[2][r] + W[8][r]);
        float tC0O = -W[5][r];
        float tP   = W[8][r];

        float dotv = st[0]*tEE + st[1]*tEO + st[2]*tOE + st[3]*tOO
                   + st[4]*tR0E + st[5]*tR0O + st[6]*tC0E + st[7]*tC0O
                   + st[8]*tP;

        // valid-count-weighted sum for the BN offset term
        float nsum = 784.f * (W[0][r] + W[1][r] + W[3][r] + W[4][r])
                   + 756.f * (W[2][r] + W[5][r] + W[6][r] + W[7][r])
                   + 729.f *  W[8][r];

        acc[r] = scale * dotv + offs * nsum;
    }

    // Bias terms: conv_b through fc (threads 0..63), and fc_b (thread 0)
    if (ci < CONV_OUT) {
        float cb = conv_b[ci];
        #pragma unroll
        for (int r = 0; r < ROUTES; ++r) acc[r] += cb * fc_w[ci * ROUTES + r];
    }
    if (ci == 0) {
        #pragma unroll
        for (int r = 0; r < ROUTES; ++r) acc[r] += fc_b[r];
    }

    // Block reduction over 256 channels
    #pragma unroll
    for (int r = 0; r < ROUTES; ++r) {
        #pragma unroll
        for (int o = 16; o > 0; o >>= 1)
            acc[r] += __shfl_xor_sync(0xFFFFFFFFu, acc[r], o);
    }
    __shared__ float red[8][ROUTES];
    const int wid = ci >> 5, lane = ci & 31;
    if (lane == 0) {
        #pragma unroll
        for (int r = 0; r < ROUTES; ++r) red[wid][r] = acc[r];
    }
    __syncthreads();
    if (ci == 0) {
        float v[ROUTES];
        #pragma unroll
        for (int r = 0; r < ROUTES; ++r) {
            float s = 0.f;
            #pragma unroll
            for (int w = 0; w < 8; ++w) s += red[w][r];
            v[r] = s;
        }
        int best = 0;
        float bv = v[0];
        #pragma unroll
        for (int r = 1; r < ROUTES; ++r)
            if (v[r] > bv) { bv = v[r]; best = r; }
        g_route[b] = best;
        #pragma unroll
        for (int r = 0; r < ROUTES; ++r) out_routing[b * ROUTES + r] = v[r];
    }
}

// ---------------------------------------------------------------------------
// Kernel 4: gather selected 64-channel slab (float4 copy), reverse scheduled
// so the tail of the input (still resident in L2 after k_stats' stream) is
// gathered first.
// grid (196, 64), 256 threads; one float4 per thread.
// ---------------------------------------------------------------------------
__global__ __launch_bounds__(256) void k_gather(const float* __restrict__ in,
                                                float* __restrict__ out)
{
    const int b = (BATCH - 1) - blockIdx.y;
    const int route = g_route[b];
    const int bx = (gridDim.x - 1) - blockIdx.x;
    const int t = bx * 256 + threadIdx.x;   // 0 .. 50175
    const int pixel = t >> 4;
    const int q = t & 15;

    const float4* src = (const float4*)in
        + ((size_t)b * (HDIM * WDIM) + pixel) * (CDIM / 4)
        + route * (ROUTE_W / 4) + q;
    float4* dst = (float4*)out + (size_t)b * (HDIM * WDIM * ROUTE_W / 4) + t;
    *dst = *src;
}

// ---------------------------------------------------------------------------
extern "C" void kernel_launch(void* const* d_in, const int* in_sizes, int n_in,
                              void* d_out, int out_size)
{
    const float* inputs  = (const float*)d_in[0];
    const float* gamma   = (const float*)d_in[1];
    const float* beta    = (const float*)d_in[2];
    const float* mmean   = (const float*)d_in[3];
    const float* mvar    = (const float*)d_in[4];
    const float* conv_w  = (const float*)d_in[5];
    const float* conv_b  = (const float*)d_in[6];
    const float* fc_w    = (const float*)d_in[7];
    const float* fc_b    = (const float*)d_in[8];

    float* out = (float*)d_out;
    // output layout: x [64,56,56,64] then routing_x [64,4]
    float* out_routing = out + ((size_t)out_size - BATCH * ROUTES);

    k_weff<<<9, CDIM>>>(conv_w, fc_w);
    k_stats<<<dim3(ROWG, BATCH), 256>>>(inputs);
    k_route<<<BATCH, CDIM>>>(gamma, beta, mmean, mvar, conv_b, fc_w, fc_b, out_routing);
    k_gather<<<dim3((HDIM * WDIM * ROUTE_W / 4) / 256, BATCH), 256>>>(inputs, out);
}